// round 3
// baseline (speedup 1.0000x reference)
#include <cuda_runtime.h>

// ---------------------------------------------------------------------------
// DynamicDWConv: conv3x3(VALID)+lrelu -> conv3x3(VALID)+lrelu -> global avg
// pool -> 1x1 conv (per-sample depthwise 3x3 kernel gen) -> depthwise conv
// SAME + bias.  B=16, C=256, H=W=64, K=3.
// Round 2: conv inner loop uses packed fma.rn.f32x2 (2x fp32 FMA throughput).
// ---------------------------------------------------------------------------

#define B_      16
#define C_      256
#define H_      64
#define W_      64
#define H1_     62          // after conv1 (VALID)
#define H2_     60          // after conv2 (VALID)
#define H1S_    64          // padded row stride for h1 scratch (float4 aligned)
#define NTILES_ 16          // conv2 spatial tiles (2 x 8)

// Scratch (allocation-free: __device__ globals)
__device__ float g_h1[(size_t)B_ * C_ * H1_ * H1S_];      // ~65 MB
__device__ float g_ppart[NTILES_ * B_ * C_];
__device__ float g_p[B_ * C_];
__device__ float g_kern[B_ * 9 * C_];

__device__ __forceinline__ float lrelu(float v) { return v > 0.f ? v : 0.1f * v; }

// ---- f32x2 packed helpers --------------------------------------------------
__device__ __forceinline__ unsigned long long pk2(float lo, float hi) {
    unsigned long long r;
    asm("mov.b64 %0, {%1, %2};" : "=l"(r) : "f"(lo), "f"(hi));
    return r;
}
__device__ __forceinline__ void upk2(unsigned long long v, float& lo, float& hi) {
    asm("mov.b64 {%0, %1}, %2;" : "=f"(lo), "=f"(hi) : "l"(v));
}
#define FMA2(acc, a, b) \
    asm("fma.rn.f32x2 %0, %1, %2, %0;" : "+l"(acc) : "l"(a), "l"(b))

// ---------------------------------------------------------------------------
// Direct 3x3 VALID conv, 256->256 channels, fp32 via f32x2.
// Block: 256 threads. Per block: 32 couts x (8 rows x 32 cols) spatial tile.
// Per thread: 8 couts x 4 pixels = 16 f32x2 accumulators.
// ---------------------------------------------------------------------------
template <bool FIRST>
__global__ __launch_bounds__(256, 2)
void conv3x3_kernel(const float* __restrict__ in_first,
                    const float* __restrict__ w,
                    const float* __restrict__ cbias)
{
    constexpr int HIN  = FIRST ? 64 : 62;
    constexpr int WIN  = FIRST ? 64 : 62;
    constexpr int INS  = 64;
    constexpr int HOUT = HIN - 2;
    constexpr int WOUT = WIN - 2;

    __shared__ float sX[8][10][35];                // conflict-free (stride-35 bijection)
    __shared__ unsigned long long sW2[32][73];     // duplicated (w,w) pairs, 72 used/row
    __shared__ float sRed[64 * 33];

    const int tid  = threadIdx.x;
    const int cg   = tid >> 6;               // cout group 0..3
    const int pg   = tid & 63;
    const int prow = pg >> 3;                // 0..7
    const int pc   = (pg & 7) << 2;          // 0,4,...,28

    const int tileX = blockIdx.x;            // 2 tiles of 32 cols
    const int tileY = blockIdx.y;            // 8 tiles of 8 rows
    const int z     = blockIdx.z;            // b * 8 + coutBlock
    const int b     = z >> 3;
    const int coutBase = (z & 7) << 5;

    const int orow  = tileY * 8 + prow;
    const int ocol0 = tileX * 32 + pc;
    const int r0 = tileY * 8;
    const int c0 = tileX * 32;

    const float* __restrict__ src = FIRST ? in_first : g_h1;

    unsigned long long acc2[8][2];
#pragma unroll
    for (int co = 0; co < 8; ++co) {
        float bv = cbias[coutBase + cg * 8 + co];
        unsigned long long bp = pk2(bv, bv);
        acc2[co][0] = bp;
        acc2[co][1] = bp;
    }

    for (int cb = 0; cb < C_; cb += 8) {
        __syncthreads();
        // ---- stage X tile: 8 cin x 10 x 34 = 2720 elements ----
        for (int idx = tid; idx < 2720; idx += 256) {
            int ci  = idx / 340;
            int rem = idx - ci * 340;
            int rr  = rem / 34;
            int cc  = rem - rr * 34;
            int r = r0 + rr, c = c0 + cc;
            float v = 0.f;
            if (r < HIN && c < WIN)
                v = src[((size_t)(b * C_ + cb + ci) * HIN + r) * INS + c];
            sX[ci][rr][cc] = v;
        }
        // ---- stage W tile: 32 cout x 8 cin x 9, duplicated pairs ----
        {
            int co_i = tid >> 3, ci_i = tid & 7;
            const float* gw = w + ((size_t)(coutBase + co_i) * C_ + cb + ci_i) * 9;
#pragma unroll
            for (int k = 0; k < 9; ++k) {
                float wv = gw[k];
                sW2[co_i][ci_i * 9 + k] = pk2(wv, wv);
            }
        }
        __syncthreads();

        // ---- compute (f32x2) ----
#pragma unroll 1
        for (int ci = 0; ci < 8; ++ci) {
#pragma unroll
            for (int ky = 0; ky < 3; ++ky) {
                float x0 = sX[ci][prow + ky][pc + 0];
                float x1 = sX[ci][prow + ky][pc + 1];
                float x2 = sX[ci][prow + ky][pc + 2];
                float x3 = sX[ci][prow + ky][pc + 3];
                float x4 = sX[ci][prow + ky][pc + 4];
                float x5 = sX[ci][prow + ky][pc + 5];
                unsigned long long p01 = pk2(x0, x1);
                unsigned long long p12 = pk2(x1, x2);
                unsigned long long p23 = pk2(x2, x3);
                unsigned long long p34 = pk2(x3, x4);
                unsigned long long p45 = pk2(x4, x5);
                // kx = 0: pairs (0,1),(2,3)
#pragma unroll
                for (int co = 0; co < 8; ++co) {
                    unsigned long long w2v = sW2[cg * 8 + co][ci * 9 + ky * 3 + 0];
                    FMA2(acc2[co][0], p01, w2v);
                    FMA2(acc2[co][1], p23, w2v);
                }
                // kx = 1: pairs (1,2),(3,4)
#pragma unroll
                for (int co = 0; co < 8; ++co) {
                    unsigned long long w2v = sW2[cg * 8 + co][ci * 9 + ky * 3 + 1];
                    FMA2(acc2[co][0], p12, w2v);
                    FMA2(acc2[co][1], p34, w2v);
                }
                // kx = 2: pairs (2,3),(4,5)
#pragma unroll
                for (int co = 0; co < 8; ++co) {
                    unsigned long long w2v = sW2[cg * 8 + co][ci * 9 + ky * 3 + 2];
                    FMA2(acc2[co][0], p23, w2v);
                    FMA2(acc2[co][1], p45, w2v);
                }
            }
        }
    }

    if (FIRST) {
        if (orow < HOUT) {
#pragma unroll
            for (int co = 0; co < 8; ++co) {
                float a0, a1, a2, a3;
                upk2(acc2[co][0], a0, a1);
                upk2(acc2[co][1], a2, a3);
                float4 v;
                v.x = lrelu(a0); v.y = lrelu(a1);
                v.z = lrelu(a2); v.w = lrelu(a3);
                size_t o = ((size_t)(b * C_ + coutBase + cg * 8 + co) * HOUT + orow) * H1S_ + ocol0;
                *reinterpret_cast<float4*>(&g_h1[o]) = v;
            }
        }
    } else {
        float part[8];
#pragma unroll
        for (int co = 0; co < 8; ++co) {
            float a[4];
            upk2(acc2[co][0], a[0], a[1]);
            upk2(acc2[co][1], a[2], a[3]);
            float s = 0.f;
#pragma unroll
            for (int j = 0; j < 4; ++j) {
                bool valid = (orow < HOUT) && (ocol0 + j < WOUT);
                if (valid) s += lrelu(a[j]);
            }
            part[co] = s;
        }
#pragma unroll
        for (int co = 0; co < 8; ++co)
            sRed[pg * 33 + cg * 8 + co] = part[co];
        __syncthreads();
        if (tid < 32) {
            float s = 0.f;
#pragma unroll 8
            for (int p = 0; p < 64; ++p) s += sRed[p * 33 + tid];
            int t = tileY * 2 + tileX;
            g_ppart[(t * B_ + b) * C_ + coutBase + tid] = s;
        }
    }
}

// ---------------------------------------------------------------------------
// reduce 16 tile partials -> pooled p[b][c] (divide by 60*60)
// ---------------------------------------------------------------------------
__global__ void reduce_p_kernel()
{
    int i = blockIdx.x * 256 + threadIdx.x;
    float s = 0.f;
#pragma unroll
    for (int t = 0; t < NTILES_; ++t) s += g_ppart[t * (B_ * C_) + i];
    g_p[i] = s * (1.0f / (H2_ * H2_));
}

// ---------------------------------------------------------------------------
// kern[b][o] = sum_c p[b][c] * w3[o][c] + b3[o]
// ---------------------------------------------------------------------------
__global__ void kern_gemm_kernel(const float* __restrict__ w3,
                                 const float* __restrict__ b3)
{
    __shared__ float sp[B_ * C_];
    const int tid  = threadIdx.x;
    const int warp = tid >> 5;
    const int lane = tid & 31;

    for (int i = tid; i < B_ * C_; i += 256) sp[i] = g_p[i];
    __syncthreads();

    int o = blockIdx.x * 8 + warp;
    float wreg[8];
#pragma unroll
    for (int i = 0; i < 8; ++i) wreg[i] = w3[(size_t)o * C_ + lane + i * 32];

    float acc[B_];
#pragma unroll
    for (int b = 0; b < B_; ++b) acc[b] = 0.f;
#pragma unroll
    for (int i = 0; i < 8; ++i) {
        int c = lane + i * 32;
        float wv = wreg[i];
#pragma unroll
        for (int b = 0; b < B_; ++b)
            acc[b] = fmaf(wv, sp[b * C_ + c], acc[b]);
    }
#pragma unroll
    for (int off = 16; off > 0; off >>= 1)
#pragma unroll
        for (int b = 0; b < B_; ++b)
            acc[b] += __shfl_xor_sync(0xFFFFFFFFu, acc[b], off);

    if (lane == 0) {
        float bb = b3[o];
#pragma unroll
        for (int b = 0; b < B_; ++b)
            g_kern[b * (9 * C_) + o] = acc[b] + bb;
    }
}

// ---------------------------------------------------------------------------
// Depthwise 3x3 SAME conv with per-(b,c) kernel + bias. One block per (b,c).
// ---------------------------------------------------------------------------
__global__ __launch_bounds__(256)
void dwconv_kernel(const float* __restrict__ x,
                   const float* __restrict__ bias,
                   float* __restrict__ out)
{
    __shared__ float sx[H_ * W_];
    __shared__ float sk[9];

    const int tid = threadIdx.x;
    const int bc  = blockIdx.x;
    const int b   = bc >> 8;
    const int c   = bc & 255;

    const float* xin = x + (size_t)bc * (H_ * W_);
    for (int i = tid; i < (H_ * W_) / 4; i += 256)
        reinterpret_cast<float4*>(sx)[i] = reinterpret_cast<const float4*>(xin)[i];
    if (tid < 9) sk[tid] = g_kern[b * (9 * C_) + c * 9 + tid];
    __syncthreads();

    const float bv = bias[c];
    float k[9];
#pragma unroll
    for (int i = 0; i < 9; ++i) k[i] = sk[i];

    for (int p = tid; p < H_ * W_; p += 256) {
        int y  = p >> 6;
        int xx = p & 63;
        float s = bv;
#pragma unroll
        for (int ky = 0; ky < 3; ++ky) {
            int yy = y + ky - 1;
            if (yy < 0 || yy >= H_) continue;
#pragma unroll
            for (int kx = 0; kx < 3; ++kx) {
                int xc = xx + kx - 1;
                if (xc < 0 || xc >= W_) continue;
                s = fmaf(k[ky * 3 + kx], sx[yy * W_ + xc], s);
            }
        }
        out[(size_t)bc * (H_ * W_) + p] = s;
    }
}

// ---------------------------------------------------------------------------
// Launch. Inputs (metadata order): x, kin, w1, b1, w2, b2, w3, b3, bias
// ---------------------------------------------------------------------------
extern "C" void kernel_launch(void* const* d_in, const int* in_sizes, int n_in,
                              void* d_out, int out_size)
{
    const float* x    = (const float*)d_in[0];
    const float* kin  = (const float*)d_in[1];
    const float* w1   = (const float*)d_in[2];
    const float* b1   = (const float*)d_in[3];
    const float* w2   = (const float*)d_in[4];
    const float* b2   = (const float*)d_in[5];
    const float* w3   = (const float*)d_in[6];
    const float* b3   = (const float*)d_in[7];
    const float* bias = (const float*)d_in[8];
    float* out = (float*)d_out;

    dim3 cgrid(2, 8, B_ * 8);
    conv3x3_kernel<true ><<<cgrid, 256>>>(kin, w1, b1);
    conv3x3_kernel<false><<<cgrid, 256>>>(nullptr, w2, b2);
    reduce_p_kernel<<<B_ * C_ / 256, 256>>>();
    kern_gemm_kernel<<<(9 * C_) / 8, 256>>>(w3, b3);
    dwconv_kernel<<<B_ * C_, 256>>>(x, bias, out);
}

// round 7
// speedup vs baseline: 3.0325x; 3.0325x over previous
#include <cuda_runtime.h>
#include <cuda_bf16.h>
#include <cstdint>

// ---------------------------------------------------------------------------
// DynamicDWConv on GB300 (compute_103 PTX => no tcgen05; mma.sync tf32)
// conv3x3(VALID)+lrelu -> conv3x3(VALID)+lrelu -> global avg pool ->
// 1x1 kernel-gen -> depthwise 3x3 SAME + bias.   B=16, C=256, H=W=64.
//
// Convs as implicit GEMM: pixels=M, couts=N, K=cin, accumulated over 9 taps.
// NHWC with pixel index n=y*64+x; tap (ky,kx) input = row slice at
// n + ky*64 + kx (shift-slice im2col). tf32 operands, fp32 accumulate.
// ---------------------------------------------------------------------------

#define B_   16
#define C_   256
#define H_   64
#define W_   64
#define FR_  4288            // 67*64 padded NHWC frame rows per batch
#define NT1_ 32              // conv1 pixel tiles (4096/128)
#define NT2_ 30              // conv2 pixel tiles (3840/128)

// Scratch (__device__ globals; allocation-free). All values tf32-rounded fp32.
__device__ float g_xT [(size_t)B_ * FR_ * C_];    // kin NHWC (~70MB)
__device__ float g_h1T[(size_t)B_ * FR_ * C_];    // lrelu(conv1) NHWC
__device__ float g_wT [2 * 9 * 256 * 256];        // [which][tap][cout][cin]
__device__ float g_ppart[NT2_ * B_ * C_];
__device__ float g_p[B_ * C_];
__device__ float g_kern[B_ * 9 * C_];

__device__ __forceinline__ float lrelu(float v) { return v > 0.f ? v : 0.1f * v; }
__device__ __forceinline__ float tf32r(float f) {
    float r;
    asm("cvt.rna.tf32.f32 %0, %1;" : "=f"(r) : "f"(f));
    return r;
}

#define MMA_TF32(d, a, bq) \
    asm volatile("mma.sync.aligned.m16n8k8.row.col.f32.tf32.tf32.f32 " \
        "{%0,%1,%2,%3}, {%4,%5,%6,%7}, {%8,%9}, {%0,%1,%2,%3};" \
        : "+f"((d)[0]), "+f"((d)[1]), "+f"((d)[2]), "+f"((d)[3]) \
        : "r"((a)[0]), "r"((a)[1]), "r"((a)[2]), "r"((a)[3]), \
          "r"((bq)[0]), "r"((bq)[1]))

// ---------------------------------------------------------------------------
// Prep: w [cout][cin][3][3] fp32 -> g_wT[which][tap][cout][cin] tf32
// ---------------------------------------------------------------------------
__global__ void prep_w_kernel(const float* __restrict__ w1, const float* __restrict__ w2)
{
    int t = blockIdx.x * 256 + threadIdx.x;
    int ci   = t & 255;
    int co   = (t >> 8) & 255;
    int rest = t >> 16;                  // 0..17
    int tap  = rest % 9;
    int which = rest / 9;
    const float* w = which ? w2 : w1;
    g_wT[t] = tf32r(w[(size_t)(co * 256 + ci) * 9 + tap]);
}

// ---------------------------------------------------------------------------
// Transpose: kin NCHW fp32 -> g_xT NHWC tf32 (padded frame rows zeroed)
// grid (67, 4, 16), 256 threads. Tile: 64 ch x 64 pixels.
// ---------------------------------------------------------------------------
__global__ void transpose_x_kernel(const float* __restrict__ kin)
{
    __shared__ float s[64][65];
    const int b = blockIdx.z, c0 = blockIdx.y * 64, n0 = blockIdx.x * 64;
    const int tid = threadIdx.x;

    if (n0 < 4096) {
#pragma unroll
        for (int i = 0; i < 16; ++i) {
            int idx = tid + i * 256, c = idx >> 6, p = idx & 63;
            s[c][p] = kin[((size_t)(b * C_ + c0 + c) << 12) + n0 + p];
        }
        __syncthreads();
#pragma unroll
        for (int i = 0; i < 16; ++i) {
            int idx = tid + i * 256, n = idx >> 6, c = idx & 63;
            g_xT[((size_t)b * FR_ + n0 + n) * C_ + c0 + c] = tf32r(s[c][n]);
        }
    } else {
#pragma unroll
        for (int i = 0; i < 16; ++i) {
            int idx = tid + i * 256, n = idx >> 6, c = idx & 63;
            g_xT[((size_t)b * FR_ + n0 + n) * C_ + c0 + c] = 0.f;
        }
    }
}

// ---------------------------------------------------------------------------
// Implicit-GEMM conv via mma.sync tf32 (m16n8k8).
// Block: 256 threads (8 warps, 2 M-warps x 4 N-warps).
// CTA tile: M=128 pixels, N=128 couts. K-loop: 9 taps x 16 chunks of 16 cin.
// Warp tile: m64 x n32 = 4x4 mma x 2 k8-steps per chunk.
// SMEM tiles: 128 rows x 16 floats, row stride 20 floats (conflict-free).
// FIRST: epilogue lrelu+bias -> g_h1T.  !FIRST: lrelu+bias + masked pool sum.
// ---------------------------------------------------------------------------
template <bool FIRST>
__global__ __launch_bounds__(256)
void conv_mma_kernel(const float* __restrict__ cbias)
{
    __shared__ __align__(16) float sbuf[2][2 * 2560];   // per buf: A(2560 fl) | B(2560 fl)
    __shared__ float sRed[2][128];

    const int tid  = threadIdx.x;
    const int lane = tid & 31;
    const int wid  = tid >> 5;
    const int mwarp = wid >> 2;          // 0..1  (pixel 64-row half)
    const int nwarp = wid & 3;           // 0..3  (cout 32-col quarter)
    const int gid   = lane >> 2;         // 0..7
    const int tig   = lane & 3;          // 0..3

    const int ntile = blockIdx.x;
    const int b     = blockIdx.y;
    const int co0   = blockIdx.z * 128;
    const int n0    = ntile * 128;

    const float* __restrict__ src  = FIRST ? g_xT : g_h1T;
    const float* __restrict__ wsrc = g_wT + (FIRST ? 0 : (size_t)9 * 256 * 256);

    // staging: thread -> row rowS (0..127), 8-float half halfS
    const int rowS  = tid >> 1;
    const int halfS = tid & 1;

    // fragment base offsets (float indices within tile)
    const int aBase = (mwarp * 64 + gid) * 20 + tig;
    const int bBase = (nwarp * 32 + gid) * 20 + tig;

    float acc[4][4][4];
#pragma unroll
    for (int mi = 0; mi < 4; ++mi)
#pragma unroll
        for (int ni = 0; ni < 4; ++ni)
#pragma unroll
            for (int j = 0; j < 4; ++j) acc[mi][ni][j] = 0.f;

    float4 ra0, ra1, rb0, rb1;
    auto loadRegs = [&](int it) {
        const int tap = it >> 4, ck = it & 15, cb = ck * 16;
        const int shift = (tap / 3) * 64 + (tap % 3);
        const float4* ag = (const float4*)(src + ((size_t)(b * FR_ + n0 + shift + rowS)) * C_ + cb);
        ra0 = ag[halfS * 2]; ra1 = ag[halfS * 2 + 1];
        const float4* bg = (const float4*)(wsrc + ((size_t)(tap * 256 + co0 + rowS)) * C_ + cb);
        rb0 = bg[halfS * 2]; rb1 = bg[halfS * 2 + 1];
    };
    auto storeTile = [&](int buf) {
        float* dA = &sbuf[buf][rowS * 20 + halfS * 8];
        ((float4*)dA)[0] = ra0; ((float4*)dA)[1] = ra1;
        float* dB = dA + 2560;
        ((float4*)dB)[0] = rb0; ((float4*)dB)[1] = rb1;
    };

    // prologue
    loadRegs(0);
    storeTile(0);

#pragma unroll 1
    for (int it = 0; it < 144; ++it) {
        __syncthreads();
        if (it < 143) loadRegs(it + 1);

        const float* Abuf = &sbuf[it & 1][0];
        const float* Bbuf = Abuf + 2560;

#pragma unroll
        for (int ks = 0; ks < 2; ++ks) {
            uint32_t af[4][4];
#pragma unroll
            for (int mi = 0; mi < 4; ++mi) {
                const float* p = Abuf + aBase + mi * 320 + ks * 8;
                af[mi][0] = __float_as_uint(p[0]);
                af[mi][1] = __float_as_uint(p[160]);
                af[mi][2] = __float_as_uint(p[4]);
                af[mi][3] = __float_as_uint(p[164]);
            }
            uint32_t bf[4][2];
#pragma unroll
            for (int ni = 0; ni < 4; ++ni) {
                const float* q = Bbuf + bBase + ni * 160 + ks * 8;
                bf[ni][0] = __float_as_uint(q[0]);
                bf[ni][1] = __float_as_uint(q[4]);
            }
#pragma unroll
            for (int mi = 0; mi < 4; ++mi)
#pragma unroll
                for (int ni = 0; ni < 4; ++ni)
                    MMA_TF32(acc[mi][ni], af[mi], bf[ni]);
        }

        if (it < 143) storeTile((it + 1) & 1);
    }

    // ---- epilogue ----
    const int prow = mwarp * 64 + gid;                 // pixel row within tile (+8 for c2/c3)
    const int ccol = co0 + nwarp * 32 + tig * 2;       // cout (pair)

    float bv0[4], bv1[4];
#pragma unroll
    for (int ni = 0; ni < 4; ++ni) { bv0[ni] = cbias[ccol + ni * 8]; bv1[ni] = cbias[ccol + ni * 8 + 1]; }

    if (FIRST) {
#pragma unroll
        for (int mi = 0; mi < 4; ++mi) {
            int na = n0 + prow + mi * 16;
            int nb = na + 8;
#pragma unroll
            for (int ni = 0; ni < 4; ++ni) {
                int cc = ccol + ni * 8;
                float2 va = make_float2(tf32r(lrelu(acc[mi][ni][0] + bv0[ni])),
                                        tf32r(lrelu(acc[mi][ni][1] + bv1[ni])));
                float2 vb = make_float2(tf32r(lrelu(acc[mi][ni][2] + bv0[ni])),
                                        tf32r(lrelu(acc[mi][ni][3] + bv1[ni])));
                *(float2*)&g_h1T[((size_t)(b * FR_ + na)) * C_ + cc] = va;
                *(float2*)&g_h1T[((size_t)(b * FR_ + nb)) * C_ + cc] = vb;
            }
        }
    } else {
        float s0[4], s1[4];
#pragma unroll
        for (int ni = 0; ni < 4; ++ni) { s0[ni] = 0.f; s1[ni] = 0.f; }
#pragma unroll
        for (int mi = 0; mi < 4; ++mi) {
            int na = n0 + prow + mi * 16;
            int nb = na + 8;
            bool va = (na & 63) < 60;
            bool vb = (nb & 63) < 60;
#pragma unroll
            for (int ni = 0; ni < 4; ++ni) {
                if (va) { s0[ni] += lrelu(acc[mi][ni][0] + bv0[ni]);
                          s1[ni] += lrelu(acc[mi][ni][1] + bv1[ni]); }
                if (vb) { s0[ni] += lrelu(acc[mi][ni][2] + bv0[ni]);
                          s1[ni] += lrelu(acc[mi][ni][3] + bv1[ni]); }
            }
        }
#pragma unroll
        for (int off = 4; off <= 16; off <<= 1)
#pragma unroll
            for (int ni = 0; ni < 4; ++ni) {
                s0[ni] += __shfl_xor_sync(0xFFFFFFFFu, s0[ni], off);
                s1[ni] += __shfl_xor_sync(0xFFFFFFFFu, s1[ni], off);
            }
        if (lane < 4) {
#pragma unroll
            for (int ni = 0; ni < 4; ++ni) {
                sRed[mwarp][nwarp * 32 + ni * 8 + lane * 2]     = s0[ni];
                sRed[mwarp][nwarp * 32 + ni * 8 + lane * 2 + 1] = s1[ni];
            }
        }
        __syncthreads();
        if (tid < 128)
            g_ppart[((size_t)ntile * B_ + b) * C_ + co0 + tid] = sRed[0][tid] + sRed[1][tid];
    }
}

// ---------------------------------------------------------------------------
// reduce 30 tile partials -> pooled p[b][c] (divide by 60*60)
// ---------------------------------------------------------------------------
__global__ void reduce_p_kernel()
{
    int i = blockIdx.x * 256 + threadIdx.x;
    float s = 0.f;
#pragma unroll
    for (int t = 0; t < NT2_; ++t) s += g_ppart[(size_t)t * (B_ * C_) + i];
    g_p[i] = s * (1.0f / 3600.0f);
}

// ---------------------------------------------------------------------------
// kern[b][o] = sum_c p[b][c] * w3[o][c] + b3[o]
// ---------------------------------------------------------------------------
__global__ void kern_gemm_kernel(const float* __restrict__ w3, const float* __restrict__ b3)
{
    __shared__ float sp[B_ * C_];
    const int tid = threadIdx.x, warp = tid >> 5, lane = tid & 31;
    for (int i = tid; i < B_ * C_; i += 256) sp[i] = g_p[i];
    __syncthreads();

    int o = blockIdx.x * 8 + warp;
    float wreg[8];
#pragma unroll
    for (int i = 0; i < 8; ++i) wreg[i] = w3[(size_t)o * C_ + lane + i * 32];
    float acc[B_];
#pragma unroll
    for (int b = 0; b < B_; ++b) acc[b] = 0.f;
#pragma unroll
    for (int i = 0; i < 8; ++i) {
        int c = lane + i * 32;
        float wv = wreg[i];
#pragma unroll
        for (int b = 0; b < B_; ++b) acc[b] = fmaf(wv, sp[b * C_ + c], acc[b]);
    }
#pragma unroll
    for (int off = 16; off > 0; off >>= 1)
#pragma unroll
        for (int b = 0; b < B_; ++b) acc[b] += __shfl_xor_sync(0xFFFFFFFFu, acc[b], off);
    if (lane == 0) {
        float bb = b3[o];
#pragma unroll
        for (int b = 0; b < B_; ++b) g_kern[b * (9 * C_) + o] = acc[b] + bb;
    }
}

// ---------------------------------------------------------------------------
// Depthwise 3x3 SAME conv, per-(b,c) kernel + bias. One block per (b,c).
// ---------------------------------------------------------------------------
__global__ __launch_bounds__(256)
void dwconv_kernel(const float* __restrict__ x, const float* __restrict__ bias,
                   float* __restrict__ out)
{
    __shared__ float sx[H_ * W_];
    __shared__ float sk[9];
    const int tid = threadIdx.x;
    const int bc = blockIdx.x, b = bc >> 8, c = bc & 255;

    const float* xin = x + (size_t)bc * (H_ * W_);
    for (int i = tid; i < (H_ * W_) / 4; i += 256)
        reinterpret_cast<float4*>(sx)[i] = reinterpret_cast<const float4*>(xin)[i];
    if (tid < 9) sk[tid] = g_kern[b * (9 * C_) + c * 9 + tid];
    __syncthreads();

    const float bv = bias[c];
    float k[9];
#pragma unroll
    for (int i = 0; i < 9; ++i) k[i] = sk[i];

    for (int p = tid; p < H_ * W_; p += 256) {
        int y = p >> 6, xx = p & 63;
        float s = bv;
#pragma unroll
        for (int ky = 0; ky < 3; ++ky) {
            int yy = y + ky - 1;
            if (yy < 0 || yy >= H_) continue;
#pragma unroll
            for (int kx = 0; kx < 3; ++kx) {
                int xc = xx + kx - 1;
                if (xc < 0 || xc >= W_) continue;
                s = fmaf(k[ky * 3 + kx], sx[yy * W_ + xc], s);
            }
        }
        out[(size_t)bc * (H_ * W_) + p] = s;
    }
}

// ---------------------------------------------------------------------------
// Launch. Inputs: x, kin, w1, b1, w2, b2, w3, b3, bias
// ---------------------------------------------------------------------------
extern "C" void kernel_launch(void* const* d_in, const int* in_sizes, int n_in,
                              void* d_out, int out_size)
{
    const float* x    = (const float*)d_in[0];
    const float* kin  = (const float*)d_in[1];
    const float* w1   = (const float*)d_in[2];
    const float* b1   = (const float*)d_in[3];
    const float* w2   = (const float*)d_in[4];
    const float* b2   = (const float*)d_in[5];
    const float* w3   = (const float*)d_in[6];
    const float* b3   = (const float*)d_in[7];
    const float* bias = (const float*)d_in[8];
    float* out = (float*)d_out;

    prep_w_kernel<<<2 * 9 * 256, 256>>>(w1, w2);
    transpose_x_kernel<<<dim3(67, 4, 16), 256>>>(kin);
    conv_mma_kernel<true ><<<dim3(NT1_, B_, 2), 256>>>(b1);
    conv_mma_kernel<false><<<dim3(NT2_, B_, 2), 256>>>(b2);
    reduce_p_kernel<<<B_ * C_ / 256, 256>>>();
    kern_gemm_kernel<<<(9 * C_) / 8, 256>>>(w3, b3);
    dwconv_kernel<<<B_ * C_, 256>>>(x, bias, out);
}

// round 8
// speedup vs baseline: 3.4928x; 1.1518x over previous
#include <cuda_runtime.h>
#include <cstdint>

// ---------------------------------------------------------------------------
// DynamicDWConv on GB300 (compute_103 PTX => mma.sync tf32 + cp.async + ldmatrix)
// conv3x3(VALID)+lrelu -> conv3x3(VALID)+lrelu -> global avg pool ->
// 1x1 kernel-gen -> depthwise 3x3 SAME + bias.   B=16, C=256, H=W=64.
//
// Convs as implicit GEMM: pixels=M, couts=N, K=cin, accumulated over 9 taps.
// NHWC with pixel index n=y*64+x; tap (ky,kx) input = row slice at
// n + ky*64 + kx (shift-slice im2col). tf32 operands, fp32 accumulate.
// ---------------------------------------------------------------------------

#define B_   16
#define C_   256
#define H_   64
#define W_   64
#define FR_  4288            // 67*64 padded NHWC frame rows per batch
#define NT1_ 32              // conv1 pixel tiles (4096/128)
#define NT2_ 30              // conv2 pixel tiles (3840/128)

// smem tile geometry: 128 rows x 32 floats, row stride 36 floats (144B)
#define ROWB_   144          // bytes per row
#define TILEB_  18432        // bytes per A (or B) tile = 128*144
#define BUFB_   36864        // bytes per (A|B) buffer

// Scratch (__device__ globals; allocation-free). All values tf32-rounded fp32.
__device__ float g_xT [(size_t)B_ * FR_ * C_];    // kin NHWC (~70MB)
__device__ float g_h1T[(size_t)B_ * FR_ * C_];    // lrelu(conv1) NHWC
__device__ float g_wT [2 * 9 * 256 * 256];        // [which][tap][cout][cin]
__device__ float g_ppart[NT2_ * B_ * C_];
__device__ float g_p[B_ * C_];
__device__ float g_kern[B_ * 9 * C_];

__device__ __forceinline__ float lrelu(float v) { return v > 0.f ? v : 0.1f * v; }
__device__ __forceinline__ float tf32r(float f) {
    float r;
    asm("cvt.rna.tf32.f32 %0, %1;" : "=f"(r) : "f"(f));
    return r;
}
__device__ __forceinline__ uint32_t smem_u32(const void* p) {
    uint32_t a;
    asm("{ .reg .u64 t; cvta.to.shared.u64 t, %1; cvt.u32.u64 %0, t; }" : "=r"(a) : "l"(p));
    return a;
}
__device__ __forceinline__ void cp16(uint32_t s, const void* g) {
    asm volatile("cp.async.cg.shared.global [%0], [%1], 16;" :: "r"(s), "l"(g) : "memory");
}
#define CP_COMMIT() asm volatile("cp.async.commit_group;" ::: "memory")
#define CP_WAIT1()  asm volatile("cp.async.wait_group 1;" ::: "memory")
#define CP_WAIT0()  asm volatile("cp.async.wait_group 0;" ::: "memory")

#define LDSM_X4(r, addr) \
    asm volatile("ldmatrix.sync.aligned.m8n8.x4.shared.b16 {%0,%1,%2,%3}, [%4];" \
        : "=r"((r)[0]), "=r"((r)[1]), "=r"((r)[2]), "=r"((r)[3]) : "r"(addr))

#define MMA_TF32(d, a, bq) \
    asm volatile("mma.sync.aligned.m16n8k8.row.col.f32.tf32.tf32.f32 " \
        "{%0,%1,%2,%3}, {%4,%5,%6,%7}, {%8,%9}, {%0,%1,%2,%3};" \
        : "+f"((d)[0]), "+f"((d)[1]), "+f"((d)[2]), "+f"((d)[3]) \
        : "r"((a)[0]), "r"((a)[1]), "r"((a)[2]), "r"((a)[3]), \
          "r"((bq)[0]), "r"((bq)[1]))

// ---------------------------------------------------------------------------
// Prep: w [cout][cin][3][3] fp32 -> g_wT[which][tap][cout][cin] tf32
// ---------------------------------------------------------------------------
__global__ void prep_w_kernel(const float* __restrict__ w1, const float* __restrict__ w2)
{
    int t = blockIdx.x * 256 + threadIdx.x;
    int ci   = t & 255;
    int co   = (t >> 8) & 255;
    int rest = t >> 16;                  // 0..17
    int tap  = rest % 9;
    int which = rest / 9;
    const float* w = which ? w2 : w1;
    g_wT[t] = tf32r(w[(size_t)(co * 256 + ci) * 9 + tap]);
}

// ---------------------------------------------------------------------------
// Transpose: kin NCHW fp32 -> g_xT NHWC tf32 (padded frame rows zeroed)
// grid (67, 4, 16), 256 threads. Tile: 64 ch x 64 pixels.
// ---------------------------------------------------------------------------
__global__ void transpose_x_kernel(const float* __restrict__ kin)
{
    __shared__ float s[64][65];
    const int b = blockIdx.z, c0 = blockIdx.y * 64, n0 = blockIdx.x * 64;
    const int tid = threadIdx.x;

    if (n0 < 4096) {
#pragma unroll
        for (int i = 0; i < 16; ++i) {
            int idx = tid + i * 256, c = idx >> 6, p = idx & 63;
            s[c][p] = kin[((size_t)(b * C_ + c0 + c) << 12) + n0 + p];
        }
        __syncthreads();
#pragma unroll
        for (int i = 0; i < 16; ++i) {
            int idx = tid + i * 256, n = idx >> 6, c = idx & 63;
            g_xT[((size_t)b * FR_ + n0 + n) * C_ + c0 + c] = tf32r(s[c][n]);
        }
    } else {
#pragma unroll
        for (int i = 0; i < 16; ++i) {
            int idx = tid + i * 256, n = idx >> 6, c = idx & 63;
            g_xT[((size_t)b * FR_ + n0 + n) * C_ + c0 + c] = 0.f;
        }
    }
}

// ---------------------------------------------------------------------------
// Implicit-GEMM conv via mma.sync tf32 (m16n8k8) + cp.async + ldmatrix.
// Block: 256 threads (8 warps, 2 M-warps x 4 N-warps).
// CTA tile: M=128 pixels, N=128 couts. K-loop: 9 taps x 8 chunks of 32 cin.
// Warp tile: m64 x n32 = 4x4 mma x 4 k8-steps per chunk.
// Dynamic smem: 2 buffers of (A tile | B tile), 128 rows x 144B each.
// FIRST: epilogue lrelu+bias -> g_h1T.  !FIRST: lrelu+bias + masked pool sum.
// ---------------------------------------------------------------------------
template <bool FIRST>
__global__ __launch_bounds__(256)
void conv_mma_kernel(const float* __restrict__ cbias)
{
    extern __shared__ __align__(16) float dsm[];
    __shared__ float sRed[2][128];

    const uint32_t sb = smem_u32(dsm);
    const int tid  = threadIdx.x;
    const int lane = tid & 31;
    const int wid  = tid >> 5;
    const int mwarp = wid >> 2;          // 0..1  (pixel 64-row half)
    const int nwarp = wid & 3;           // 0..3  (cout 32-col quarter)
    const int gid   = lane >> 2;         // 0..7
    const int tig   = lane & 3;          // 0..3

    const int ntile = blockIdx.x;
    const int b     = blockIdx.y;
    const int co0   = blockIdx.z * 128;
    const int n0    = ntile * 128;

    const float* __restrict__ src  = FIRST ? g_xT : g_h1T;
    const float* __restrict__ wsrc = g_wT + (FIRST ? 0 : (size_t)9 * 256 * 256);

    // staging: thread -> row rowS (0..127), 64B half (16 floats)
    const int rowS  = tid >> 1;
    const int halfS = (tid & 1) * 16;    // float offset within 32-float row
    const uint32_t stA = sb + (uint32_t)rowS * ROWB_ + (uint32_t)halfS * 4;
    const uint32_t stB = stA + TILEB_;

    // ldmatrix lane addresses (within tile)
    const uint32_t aAddr = sb + (uint32_t)(mwarp * 64 + (lane & 15)) * ROWB_
                              + (uint32_t)(lane >> 4) * 16;
    const uint32_t bAddr = sb + TILEB_
                              + (uint32_t)(nwarp * 32 + ((lane >> 4) << 3) + (lane & 7)) * ROWB_
                              + (uint32_t)((lane >> 3) & 1) * 16;

    float acc[4][4][4];
#pragma unroll
    for (int mi = 0; mi < 4; ++mi)
#pragma unroll
        for (int ni = 0; ni < 4; ++ni)
#pragma unroll
            for (int j = 0; j < 4; ++j) acc[mi][ni][j] = 0.f;

    auto stage = [&](int it, int buf) {
        const int tap = it >> 3, ck = it & 7, cb = ck * 32;
        const int shift = (tap / 3) * 64 + (tap % 3);
        const uint32_t o = (uint32_t)buf * BUFB_;
        const float* gA = src + ((size_t)(b * FR_ + n0 + shift + rowS)) * C_ + cb + halfS;
        const float* gB = wsrc + ((size_t)(tap * 256 + co0 + rowS)) * C_ + cb + halfS;
#pragma unroll
        for (int j = 0; j < 4; ++j) cp16(stA + o + j * 16, gA + j * 4);
#pragma unroll
        for (int j = 0; j < 4; ++j) cp16(stB + o + j * 16, gB + j * 4);
    };

    // prologue
    stage(0, 0);
    CP_COMMIT();

#pragma unroll 1
    for (int it = 0; it < 72; ++it) {
        if (it < 71) { stage(it + 1, (it + 1) & 1); CP_COMMIT(); CP_WAIT1(); }
        else         { CP_WAIT0(); }
        __syncthreads();

        const uint32_t Ab = aAddr + (uint32_t)(it & 1) * BUFB_;
        const uint32_t Bb = bAddr + (uint32_t)(it & 1) * BUFB_;

#pragma unroll
        for (int ks = 0; ks < 4; ++ks) {
            uint32_t af[4][4];
#pragma unroll
            for (int mi = 0; mi < 4; ++mi)
                LDSM_X4(af[mi], Ab + (uint32_t)mi * (16 * ROWB_) + (uint32_t)ks * 32);
            uint32_t bf[4][2];
#pragma unroll
            for (int np = 0; np < 2; ++np) {
                uint32_t t4[4];
                LDSM_X4(t4, Bb + (uint32_t)np * (16 * ROWB_) + (uint32_t)ks * 32);
                bf[np * 2][0]     = t4[0]; bf[np * 2][1]     = t4[1];
                bf[np * 2 + 1][0] = t4[2]; bf[np * 2 + 1][1] = t4[3];
            }
#pragma unroll
            for (int mi = 0; mi < 4; ++mi)
#pragma unroll
                for (int ni = 0; ni < 4; ++ni)
                    MMA_TF32(acc[mi][ni], af[mi], bf[ni]);
        }
        __syncthreads();
    }

    // ---- epilogue ----
    const int prow = mwarp * 64 + gid;                 // pixel row within tile (+8 for c2/c3)
    const int ccol = co0 + nwarp * 32 + tig * 2;       // cout (pair)

    float bv0[4], bv1[4];
#pragma unroll
    for (int ni = 0; ni < 4; ++ni) { bv0[ni] = cbias[ccol + ni * 8]; bv1[ni] = cbias[ccol + ni * 8 + 1]; }

    if (FIRST) {
#pragma unroll
        for (int mi = 0; mi < 4; ++mi) {
            int na = n0 + prow + mi * 16;
            int nb = na + 8;
#pragma unroll
            for (int ni = 0; ni < 4; ++ni) {
                int cc = ccol + ni * 8;
                float2 va = make_float2(tf32r(lrelu(acc[mi][ni][0] + bv0[ni])),
                                        tf32r(lrelu(acc[mi][ni][1] + bv1[ni])));
                float2 vb = make_float2(tf32r(lrelu(acc[mi][ni][2] + bv0[ni])),
                                        tf32r(lrelu(acc[mi][ni][3] + bv1[ni])));
                *(float2*)&g_h1T[((size_t)(b * FR_ + na)) * C_ + cc] = va;
                *(float2*)&g_h1T[((size_t)(b * FR_ + nb)) * C_ + cc] = vb;
            }
        }
    } else {
        float s0[4], s1[4];
#pragma unroll
        for (int ni = 0; ni < 4; ++ni) { s0[ni] = 0.f; s1[ni] = 0.f; }
#pragma unroll
        for (int mi = 0; mi < 4; ++mi) {
            int na = n0 + prow + mi * 16;
            int nb = na + 8;
            bool va = (na & 63) < 60;
            bool vb = (nb & 63) < 60;
#pragma unroll
            for (int ni = 0; ni < 4; ++ni) {
                if (va) { s0[ni] += lrelu(acc[mi][ni][0] + bv0[ni]);
                          s1[ni] += lrelu(acc[mi][ni][1] + bv1[ni]); }
                if (vb) { s0[ni] += lrelu(acc[mi][ni][2] + bv0[ni]);
                          s1[ni] += lrelu(acc[mi][ni][3] + bv1[ni]); }
            }
        }
#pragma unroll
        for (int off = 4; off <= 16; off <<= 1)
#pragma unroll
            for (int ni = 0; ni < 4; ++ni) {
                s0[ni] += __shfl_xor_sync(0xFFFFFFFFu, s0[ni], off);
                s1[ni] += __shfl_xor_sync(0xFFFFFFFFu, s1[ni], off);
            }
        if (lane < 4) {
#pragma unroll
            for (int ni = 0; ni < 4; ++ni) {
                sRed[mwarp][nwarp * 32 + ni * 8 + lane * 2]     = s0[ni];
                sRed[mwarp][nwarp * 32 + ni * 8 + lane * 2 + 1] = s1[ni];
            }
        }
        __syncthreads();
        if (tid < 128)
            g_ppart[((size_t)ntile * B_ + b) * C_ + co0 + tid] = sRed[0][tid] + sRed[1][tid];
    }
}

// ---------------------------------------------------------------------------
// reduce 30 tile partials -> pooled p[b][c] (divide by 60*60)
// ---------------------------------------------------------------------------
__global__ void reduce_p_kernel()
{
    int i = blockIdx.x * 256 + threadIdx.x;
    float s = 0.f;
#pragma unroll
    for (int t = 0; t < NT2_; ++t) s += g_ppart[(size_t)t * (B_ * C_) + i];
    g_p[i] = s * (1.0f / 3600.0f);
}

// ---------------------------------------------------------------------------
// kern[b][o] = sum_c p[b][c] * w3[o][c] + b3[o]
// ---------------------------------------------------------------------------
__global__ void kern_gemm_kernel(const float* __restrict__ w3, const float* __restrict__ b3)
{
    __shared__ float sp[B_ * C_];
    const int tid = threadIdx.x, warp = tid >> 5, lane = tid & 31;
    for (int i = tid; i < B_ * C_; i += 256) sp[i] = g_p[i];
    __syncthreads();

    int o = blockIdx.x * 8 + warp;
    float wreg[8];
#pragma unroll
    for (int i = 0; i < 8; ++i) wreg[i] = w3[(size_t)o * C_ + lane + i * 32];
    float acc[B_];
#pragma unroll
    for (int b = 0; b < B_; ++b) acc[b] = 0.f;
#pragma unroll
    for (int i = 0; i < 8; ++i) {
        int c = lane + i * 32;
        float wv = wreg[i];
#pragma unroll
        for (int b = 0; b < B_; ++b) acc[b] = fmaf(wv, sp[b * C_ + c], acc[b]);
    }
#pragma unroll
    for (int off = 16; off > 0; off >>= 1)
#pragma unroll
        for (int b = 0; b < B_; ++b) acc[b] += __shfl_xor_sync(0xFFFFFFFFu, acc[b], off);
    if (lane == 0) {
        float bb = b3[o];
#pragma unroll
        for (int b = 0; b < B_; ++b) g_kern[b * (9 * C_) + o] = acc[b] + bb;
    }
}

// ---------------------------------------------------------------------------
// Depthwise 3x3 SAME conv, per-(b,c) kernel + bias. One block per (b,c).
// ---------------------------------------------------------------------------
__global__ __launch_bounds__(256)
void dwconv_kernel(const float* __restrict__ x, const float* __restrict__ bias,
                   float* __restrict__ out)
{
    __shared__ float sx[H_ * W_];
    __shared__ float sk[9];
    const int tid = threadIdx.x;
    const int bc = blockIdx.x, b = bc >> 8, c = bc & 255;

    const float* xin = x + (size_t)bc * (H_ * W_);
    for (int i = tid; i < (H_ * W_) / 4; i += 256)
        reinterpret_cast<float4*>(sx)[i] = reinterpret_cast<const float4*>(xin)[i];
    if (tid < 9) sk[tid] = g_kern[b * (9 * C_) + c * 9 + tid];
    __syncthreads();

    const float bv = bias[c];
    float k[9];
#pragma unroll
    for (int i = 0; i < 9; ++i) k[i] = sk[i];

    for (int p = tid; p < H_ * W_; p += 256) {
        int y = p >> 6, xx = p & 63;
        float s = bv;
#pragma unroll
        for (int ky = 0; ky < 3; ++ky) {
            int yy = y + ky - 1;
            if (yy < 0 || yy >= H_) continue;
#pragma unroll
            for (int kx = 0; kx < 3; ++kx) {
                int xc = xx + kx - 1;
                if (xc < 0 || xc >= W_) continue;
                s = fmaf(k[ky * 3 + kx], sx[yy * W_ + xc], s);
            }
        }
        out[(size_t)bc * (H_ * W_) + p] = s;
    }
}

// ---------------------------------------------------------------------------
// Launch. Inputs: x, kin, w1, b1, w2, b2, w3, b3, bias
// ---------------------------------------------------------------------------
extern "C" void kernel_launch(void* const* d_in, const int* in_sizes, int n_in,
                              void* d_out, int out_size)
{
    const float* x    = (const float*)d_in[0];
    const float* kin  = (const float*)d_in[1];
    const float* w1   = (const float*)d_in[2];
    const float* b1   = (const float*)d_in[3];
    const float* w2   = (const float*)d_in[4];
    const float* b2   = (const float*)d_in[5];
    const float* w3   = (const float*)d_in[6];
    const float* b3   = (const float*)d_in[7];
    const float* bias = (const float*)d_in[8];
    float* out = (float*)d_out;

    const int SMEM_CONV = 2 * BUFB_;    // 73728 B dynamic
    cudaFuncSetAttribute(conv_mma_kernel<true>,  cudaFuncAttributeMaxDynamicSharedMemorySize, SMEM_CONV);
    cudaFuncSetAttribute(conv_mma_kernel<false>, cudaFuncAttributeMaxDynamicSharedMemorySize, SMEM_CONV);

    prep_w_kernel<<<2 * 9 * 256, 256>>>(w1, w2);
    transpose_x_kernel<<<dim3(67, 4, 16), 256>>>(kin);
    conv_mma_kernel<true ><<<dim3(NT1_, B_, 2), 256, SMEM_CONV>>>(b1);
    conv_mma_kernel<false><<<dim3(NT2_, B_, 2), 256, SMEM_CONV>>>(b2);
    reduce_p_kernel<<<B_ * C_ / 256, 256>>>();
    kern_gemm_kernel<<<(9 * C_) / 8, 256>>>(w3, b3);
    dwconv_kernel<<<B_ * C_, 256>>>(x, bias, out);
}

// round 9
// speedup vs baseline: 3.6352x; 1.0408x over previous
#include <cuda_runtime.h>
#include <cstdint>

// ---------------------------------------------------------------------------
// DynamicDWConv on GB300 (compute_103 PTX => mma.sync tf32 + cp.async + ldmatrix)
// conv3x3(VALID)+lrelu -> conv3x3(VALID)+lrelu -> global avg pool ->
// 1x1 kernel-gen -> depthwise 3x3 SAME + bias.   B=16, C=256, H=W=64.
//
// Convs as implicit GEMM: pixels=M, couts=N, K=cin, accumulated over 9 taps.
// NHWC with pixel index n=y*64+x; tap (ky,kx) input = row slice at
// n + ky*64 + kx (shift-slice im2col). tf32 operands, fp32 accumulate.
// Round 8: 3-stage cp.async pipeline, one barrier per mainloop iteration.
// ---------------------------------------------------------------------------

#define B_   16
#define C_   256
#define H_   64
#define W_   64
#define FR_  4288            // 67*64 padded NHWC frame rows per batch
#define NT1_ 32              // conv1 pixel tiles (4096/128)
#define NT2_ 30              // conv2 pixel tiles (3840/128)

// smem tile geometry: 128 rows x 32 floats, row stride 36 floats (144B)
#define ROWB_   144          // bytes per row
#define TILEB_  18432        // bytes per A (or B) tile = 128*144
#define BUFB_   36864        // bytes per (A|B) buffer
#define NSTAGE_ 3

// Scratch (__device__ globals; allocation-free). All values tf32-rounded fp32.
__device__ float g_xT [(size_t)B_ * FR_ * C_];    // kin NHWC (~70MB)
__device__ float g_h1T[(size_t)B_ * FR_ * C_];    // lrelu(conv1) NHWC
__device__ float g_wT [2 * 9 * 256 * 256];        // [which][tap][cout][cin]
__device__ float g_ppart[NT2_ * B_ * C_];
__device__ float g_p[B_ * C_];
__device__ float g_kern[B_ * 9 * C_];

__device__ __forceinline__ float lrelu(float v) { return v > 0.f ? v : 0.1f * v; }
__device__ __forceinline__ float tf32r(float f) {
    float r;
    asm("cvt.rna.tf32.f32 %0, %1;" : "=f"(r) : "f"(f));
    return r;
}
__device__ __forceinline__ uint32_t smem_u32(const void* p) {
    uint32_t a;
    asm("{ .reg .u64 t; cvta.to.shared.u64 t, %1; cvt.u32.u64 %0, t; }" : "=r"(a) : "l"(p));
    return a;
}
__device__ __forceinline__ void cp16(uint32_t s, const void* g) {
    asm volatile("cp.async.cg.shared.global [%0], [%1], 16;" :: "r"(s), "l"(g) : "memory");
}
#define CP_COMMIT() asm volatile("cp.async.commit_group;" ::: "memory")
#define CP_WAIT1()  asm volatile("cp.async.wait_group 1;" ::: "memory")

#define LDSM_X4(r, addr) \
    asm volatile("ldmatrix.sync.aligned.m8n8.x4.shared.b16 {%0,%1,%2,%3}, [%4];" \
        : "=r"((r)[0]), "=r"((r)[1]), "=r"((r)[2]), "=r"((r)[3]) : "r"(addr))

#define MMA_TF32(d, a, bq) \
    asm volatile("mma.sync.aligned.m16n8k8.row.col.f32.tf32.tf32.f32 " \
        "{%0,%1,%2,%3}, {%4,%5,%6,%7}, {%8,%9}, {%0,%1,%2,%3};" \
        : "+f"((d)[0]), "+f"((d)[1]), "+f"((d)[2]), "+f"((d)[3]) \
        : "r"((a)[0]), "r"((a)[1]), "r"((a)[2]), "r"((a)[3]), \
          "r"((bq)[0]), "r"((bq)[1]))

// ---------------------------------------------------------------------------
// Prep: w [cout][cin][3][3] fp32 -> g_wT[which][tap][cout][cin] tf32
// ---------------------------------------------------------------------------
__global__ void prep_w_kernel(const float* __restrict__ w1, const float* __restrict__ w2)
{
    int t = blockIdx.x * 256 + threadIdx.x;
    int ci   = t & 255;
    int co   = (t >> 8) & 255;
    int rest = t >> 16;                  // 0..17
    int tap  = rest % 9;
    int which = rest / 9;
    const float* w = which ? w2 : w1;
    g_wT[t] = tf32r(w[(size_t)(co * 256 + ci) * 9 + tap]);
}

// ---------------------------------------------------------------------------
// Transpose: kin NCHW fp32 -> g_xT NHWC tf32 (padded frame rows zeroed)
// grid (67, 4, 16), 256 threads. Tile: 64 ch x 64 pixels.
// ---------------------------------------------------------------------------
__global__ void transpose_x_kernel(const float* __restrict__ kin)
{
    __shared__ float s[64][65];
    const int b = blockIdx.z, c0 = blockIdx.y * 64, n0 = blockIdx.x * 64;
    const int tid = threadIdx.x;

    if (n0 < 4096) {
#pragma unroll
        for (int i = 0; i < 16; ++i) {
            int idx = tid + i * 256, c = idx >> 6, p = idx & 63;
            s[c][p] = kin[((size_t)(b * C_ + c0 + c) << 12) + n0 + p];
        }
        __syncthreads();
#pragma unroll
        for (int i = 0; i < 16; ++i) {
            int idx = tid + i * 256, n = idx >> 6, c = idx & 63;
            g_xT[((size_t)b * FR_ + n0 + n) * C_ + c0 + c] = tf32r(s[c][n]);
        }
    } else {
#pragma unroll
        for (int i = 0; i < 16; ++i) {
            int idx = tid + i * 256, n = idx >> 6, c = idx & 63;
            g_xT[((size_t)b * FR_ + n0 + n) * C_ + c0 + c] = 0.f;
        }
    }
}

// ---------------------------------------------------------------------------
// Implicit-GEMM conv via mma.sync tf32 (m16n8k8) + 3-stage cp.async + ldmatrix.
// Block: 256 threads (8 warps, 2 M-warps x 4 N-warps).
// CTA tile: M=128 pixels, N=128 couts. K-loop: 9 taps x 8 chunks of 32 cin.
// Warp tile: m64 x n32 = 4x4 mma x 4 k8-steps per chunk.
// Dynamic smem: 3 buffers of (A tile | B tile), 128 rows x 144B each.
// Mainloop (one barrier/iter): wait(1) -> sync -> stage(it+2) -> compute(it).
// FIRST: epilogue lrelu+bias -> g_h1T.  !FIRST: lrelu+bias + masked pool sum.
// ---------------------------------------------------------------------------
template <bool FIRST>
__global__ __launch_bounds__(256)
void conv_mma_kernel(const float* __restrict__ cbias)
{
    extern __shared__ __align__(16) float dsm[];
    __shared__ float sRed[2][128];

    const uint32_t sb = smem_u32(dsm);
    const int tid  = threadIdx.x;
    const int lane = tid & 31;
    const int wid  = tid >> 5;
    const int mwarp = wid >> 2;          // 0..1  (pixel 64-row half)
    const int nwarp = wid & 3;           // 0..3  (cout 32-col quarter)
    const int gid   = lane >> 2;         // 0..7
    const int tig   = lane & 3;          // 0..3

    const int ntile = blockIdx.x;
    const int b     = blockIdx.y;
    const int co0   = blockIdx.z * 128;
    const int n0    = ntile * 128;

    const float* __restrict__ src  = FIRST ? g_xT : g_h1T;
    const float* __restrict__ wsrc = g_wT + (FIRST ? 0 : (size_t)9 * 256 * 256);

    // staging: thread -> row rowS (0..127), 64B half (16 floats)
    const int rowS  = tid >> 1;
    const int halfS = (tid & 1) * 16;    // float offset within 32-float row
    const uint32_t stA = sb + (uint32_t)rowS * ROWB_ + (uint32_t)halfS * 4;
    const uint32_t stB = stA + TILEB_;

    // ldmatrix lane addresses (within tile)
    const uint32_t aAddr = sb + (uint32_t)(mwarp * 64 + (lane & 15)) * ROWB_
                              + (uint32_t)(lane >> 4) * 16;
    const uint32_t bAddr = sb + TILEB_
                              + (uint32_t)(nwarp * 32 + ((lane >> 4) << 3) + (lane & 7)) * ROWB_
                              + (uint32_t)((lane >> 3) & 1) * 16;

    float acc[4][4][4];
#pragma unroll
    for (int mi = 0; mi < 4; ++mi)
#pragma unroll
        for (int ni = 0; ni < 4; ++ni)
#pragma unroll
            for (int j = 0; j < 4; ++j) acc[mi][ni][j] = 0.f;

    auto stage = [&](int it, int buf) {
        const int tap = it >> 3, ck = it & 7, cb = ck * 32;
        const int shift = (tap / 3) * 64 + (tap % 3);
        const uint32_t o = (uint32_t)buf * BUFB_;
        const float* gA = src + ((size_t)(b * FR_ + n0 + shift + rowS)) * C_ + cb + halfS;
        const float* gB = wsrc + ((size_t)(tap * 256 + co0 + rowS)) * C_ + cb + halfS;
#pragma unroll
        for (int j = 0; j < 4; ++j) cp16(stA + o + j * 16, gA + j * 4);
#pragma unroll
        for (int j = 0; j < 4; ++j) cp16(stB + o + j * 16, gB + j * 4);
    };

    // prologue: fill stages 0 and 1
    stage(0, 0); CP_COMMIT();
    stage(1, 1); CP_COMMIT();

    int buf = 0;
#pragma unroll 1
    for (int it = 0; it < 72; ++it) {
        CP_WAIT1();            // group 'it' complete (<=1 pending: group it+1)
        __syncthreads();       // visibility + all warps done reading buf (it-1)%3

        if (it < 70) {
            int nb = buf + 2; if (nb >= NSTAGE_) nb -= NSTAGE_;
            stage(it + 2, nb);
        }
        CP_COMMIT();

        const uint32_t Ab = aAddr + (uint32_t)buf * BUFB_;
        const uint32_t Bb = bAddr + (uint32_t)buf * BUFB_;

#pragma unroll
        for (int ks = 0; ks < 4; ++ks) {
            uint32_t af[4][4];
#pragma unroll
            for (int mi = 0; mi < 4; ++mi)
                LDSM_X4(af[mi], Ab + (uint32_t)mi * (16 * ROWB_) + (uint32_t)ks * 32);
            uint32_t bf[4][2];
#pragma unroll
            for (int np = 0; np < 2; ++np) {
                uint32_t t4[4];
                LDSM_X4(t4, Bb + (uint32_t)np * (16 * ROWB_) + (uint32_t)ks * 32);
                bf[np * 2][0]     = t4[0]; bf[np * 2][1]     = t4[1];
                bf[np * 2 + 1][0] = t4[2]; bf[np * 2 + 1][1] = t4[3];
            }
#pragma unroll
            for (int mi = 0; mi < 4; ++mi)
#pragma unroll
                for (int ni = 0; ni < 4; ++ni)
                    MMA_TF32(acc[mi][ni], af[mi], bf[ni]);
        }

        if (++buf >= NSTAGE_) buf = 0;
    }

    // ---- epilogue ----
    const int prow = mwarp * 64 + gid;                 // pixel row within tile (+8 for c2/c3)
    const int ccol = co0 + nwarp * 32 + tig * 2;       // cout (pair)

    float bv0[4], bv1[4];
#pragma unroll
    for (int ni = 0; ni < 4; ++ni) { bv0[ni] = cbias[ccol + ni * 8]; bv1[ni] = cbias[ccol + ni * 8 + 1]; }

    if (FIRST) {
#pragma unroll
        for (int mi = 0; mi < 4; ++mi) {
            int na = n0 + prow + mi * 16;
            int nb = na + 8;
#pragma unroll
            for (int ni = 0; ni < 4; ++ni) {
                int cc = ccol + ni * 8;
                float2 va = make_float2(tf32r(lrelu(acc[mi][ni][0] + bv0[ni])),
                                        tf32r(lrelu(acc[mi][ni][1] + bv1[ni])));
                float2 vb = make_float2(tf32r(lrelu(acc[mi][ni][2] + bv0[ni])),
                                        tf32r(lrelu(acc[mi][ni][3] + bv1[ni])));
                *(float2*)&g_h1T[((size_t)(b * FR_ + na)) * C_ + cc] = va;
                *(float2*)&g_h1T[((size_t)(b * FR_ + nb)) * C_ + cc] = vb;
            }
        }
    } else {
        float s0[4], s1[4];
#pragma unroll
        for (int ni = 0; ni < 4; ++ni) { s0[ni] = 0.f; s1[ni] = 0.f; }
#pragma unroll
        for (int mi = 0; mi < 4; ++mi) {
            int na = n0 + prow + mi * 16;
            int nb = na + 8;
            bool va = (na & 63) < 60;
            bool vb = (nb & 63) < 60;
#pragma unroll
            for (int ni = 0; ni < 4; ++ni) {
                if (va) { s0[ni] += lrelu(acc[mi][ni][0] + bv0[ni]);
                          s1[ni] += lrelu(acc[mi][ni][1] + bv1[ni]); }
                if (vb) { s0[ni] += lrelu(acc[mi][ni][2] + bv0[ni]);
                          s1[ni] += lrelu(acc[mi][ni][3] + bv1[ni]); }
            }
        }
#pragma unroll
        for (int off = 4; off <= 16; off <<= 1)
#pragma unroll
            for (int ni = 0; ni < 4; ++ni) {
                s0[ni] += __shfl_xor_sync(0xFFFFFFFFu, s0[ni], off);
                s1[ni] += __shfl_xor_sync(0xFFFFFFFFu, s1[ni], off);
            }
        if (lane < 4) {
#pragma unroll
            for (int ni = 0; ni < 4; ++ni) {
                sRed[mwarp][nwarp * 32 + ni * 8 + lane * 2]     = s0[ni];
                sRed[mwarp][nwarp * 32 + ni * 8 + lane * 2 + 1] = s1[ni];
            }
        }
        __syncthreads();
        if (tid < 128)
            g_ppart[((size_t)ntile * B_ + b) * C_ + co0 + tid] = sRed[0][tid] + sRed[1][tid];
    }
}

// ---------------------------------------------------------------------------
// reduce 30 tile partials -> pooled p[b][c] (divide by 60*60)
// ---------------------------------------------------------------------------
__global__ void reduce_p_kernel()
{
    int i = blockIdx.x * 256 + threadIdx.x;
    float s = 0.f;
#pragma unroll
    for (int t = 0; t < NT2_; ++t) s += g_ppart[(size_t)t * (B_ * C_) + i];
    g_p[i] = s * (1.0f / 3600.0f);
}

// ---------------------------------------------------------------------------
// kern[b][o] = sum_c p[b][c] * w3[o][c] + b3[o]
// ---------------------------------------------------------------------------
__global__ void kern_gemm_kernel(const float* __restrict__ w3, const float* __restrict__ b3)
{
    __shared__ float sp[B_ * C_];
    const int tid = threadIdx.x, warp = tid >> 5, lane = tid & 31;
    for (int i = tid; i < B_ * C_; i += 256) sp[i] = g_p[i];
    __syncthreads();

    int o = blockIdx.x * 8 + warp;
    float wreg[8];
#pragma unroll
    for (int i = 0; i < 8; ++i) wreg[i] = w3[(size_t)o * C_ + lane + i * 32];
    float acc[B_];
#pragma unroll
    for (int b = 0; b < B_; ++b) acc[b] = 0.f;
#pragma unroll
    for (int i = 0; i < 8; ++i) {
        int c = lane + i * 32;
        float wv = wreg[i];
#pragma unroll
        for (int b = 0; b < B_; ++b) acc[b] = fmaf(wv, sp[b * C_ + c], acc[b]);
    }
#pragma unroll
    for (int off = 16; off > 0; off >>= 1)
#pragma unroll
        for (int b = 0; b < B_; ++b) acc[b] += __shfl_xor_sync(0xFFFFFFFFu, acc[b], off);
    if (lane == 0) {
        float bb = b3[o];
#pragma unroll
        for (int b = 0; b < B_; ++b) g_kern[b * (9 * C_) + o] = acc[b] + bb;
    }
}

// ---------------------------------------------------------------------------
// Depthwise 3x3 SAME conv, per-(b,c) kernel + bias. One block per (b,c).
// ---------------------------------------------------------------------------
__global__ __launch_bounds__(256)
void dwconv_kernel(const float* __restrict__ x, const float* __restrict__ bias,
                   float* __restrict__ out)
{
    __shared__ float sx[H_ * W_];
    __shared__ float sk[9];
    const int tid = threadIdx.x;
    const int bc = blockIdx.x, b = bc >> 8, c = bc & 255;

    const float* xin = x + (size_t)bc * (H_ * W_);
    for (int i = tid; i < (H_ * W_) / 4; i += 256)
        reinterpret_cast<float4*>(sx)[i] = reinterpret_cast<const float4*>(xin)[i];
    if (tid < 9) sk[tid] = g_kern[b * (9 * C_) + c * 9 + tid];
    __syncthreads();

    const float bv = bias[c];
    float k[9];
#pragma unroll
    for (int i = 0; i < 9; ++i) k[i] = sk[i];

    for (int p = tid; p < H_ * W_; p += 256) {
        int y = p >> 6, xx = p & 63;
        float s = bv;
#pragma unroll
        for (int ky = 0; ky < 3; ++ky) {
            int yy = y + ky - 1;
            if (yy < 0 || yy >= H_) continue;
#pragma unroll
            for (int kx = 0; kx < 3; ++kx) {
                int xc = xx + kx - 1;
                if (xc < 0 || xc >= W_) continue;
                s = fmaf(k[ky * 3 + kx], sx[yy * W_ + xc], s);
            }
        }
        out[(size_t)bc * (H_ * W_) + p] = s;
    }
}

// ---------------------------------------------------------------------------
// Launch. Inputs: x, kin, w1, b1, w2, b2, w3, b3, bias
// ---------------------------------------------------------------------------
extern "C" void kernel_launch(void* const* d_in, const int* in_sizes, int n_in,
                              void* d_out, int out_size)
{
    const float* x    = (const float*)d_in[0];
    const float* kin  = (const float*)d_in[1];
    const float* w1   = (const float*)d_in[2];
    const float* b1   = (const float*)d_in[3];
    const float* w2   = (const float*)d_in[4];
    const float* b2   = (const float*)d_in[5];
    const float* w3   = (const float*)d_in[6];
    const float* b3   = (const float*)d_in[7];
    const float* bias = (const float*)d_in[8];
    float* out = (float*)d_out;

    const int SMEM_CONV = NSTAGE_ * BUFB_;    // 110592 B dynamic
    cudaFuncSetAttribute(conv_mma_kernel<true>,  cudaFuncAttributeMaxDynamicSharedMemorySize, SMEM_CONV);
    cudaFuncSetAttribute(conv_mma_kernel<false>, cudaFuncAttributeMaxDynamicSharedMemorySize, SMEM_CONV);

    prep_w_kernel<<<2 * 9 * 256, 256>>>(w1, w2);
    transpose_x_kernel<<<dim3(67, 4, 16), 256>>>(kin);
    conv_mma_kernel<true ><<<dim3(NT1_, B_, 2), 256, SMEM_CONV>>>(b1);
    conv_mma_kernel<false><<<dim3(NT2_, B_, 2), 256, SMEM_CONV>>>(b2);
    reduce_p_kernel<<<B_ * C_ / 256, 256>>>();
    kern_gemm_kernel<<<(9 * C_) / 8, 256>>>(w3, b3);
    dwconv_kernel<<<B_ * C_, 256>>>(x, bias, out);
}

// round 11
// speedup vs baseline: 6.7812x; 1.8654x over previous
#include <cuda_runtime.h>
#include <cuda_fp16.h>
#include <cstdint>

// ---------------------------------------------------------------------------
// DynamicDWConv on GB300 (compute_103 PTX => mma.sync fp16 + cp.async + ldmatrix)
// conv3x3(VALID)+lrelu -> conv3x3(VALID)+lrelu -> global avg pool ->
// 1x1 kernel-gen -> depthwise 3x3 SAME + bias.   B=16, C=256, H=W=64.
//
// Convs as implicit GEMM: pixels=M, couts=N, K=cin, accumulated over 9 taps.
// NHWC with pixel index n=y*64+x; tap (ky,kx) input = row slice at
// n + ky*64 + kx (shift-slice im2col). fp16 operands (10-bit mantissa = tf32),
// fp32 accumulate. 3-stage cp.async pipeline, k=64 per stage.
// ---------------------------------------------------------------------------

#define B_   16
#define C_   256
#define H_   64
#define W_   64
#define FR_  4288            // 67*64 padded NHWC frame rows per batch
#define NT1_ 32              // conv1 pixel tiles (4096/128)
#define NT2_ 30              // conv2 pixel tiles (3840/128)

// smem tile geometry: 128 rows x 64 halves (128B), row stride 144B
#define ROWB_   144
#define TILEB_  18432        // 128*144 per A (or B) tile
#define BUFB_   36864        // A|B buffer
#define NSTAGE_ 3

// Scratch (__device__ globals; allocation-free). fp16 operands.
__device__ __half g_xT [(size_t)B_ * FR_ * C_];   // kin NHWC (~35MB)
__device__ __half g_h1T[(size_t)B_ * FR_ * C_];   // lrelu(conv1) NHWC
__device__ __half g_wT [2 * 9 * 256 * 256];       // [which][tap][cout][cin]
__device__ float g_ppart[NT2_ * B_ * C_];
__device__ float g_p[B_ * C_];
__device__ float g_kern[B_ * 9 * C_];

__device__ __forceinline__ float lrelu(float v) { return v > 0.f ? v : 0.1f * v; }
__device__ __forceinline__ uint32_t smem_u32(const void* p) {
    uint32_t a;
    asm("{ .reg .u64 t; cvta.to.shared.u64 t, %1; cvt.u32.u64 %0, t; }" : "=r"(a) : "l"(p));
    return a;
}
__device__ __forceinline__ void cp16(uint32_t s, const void* g) {
    asm volatile("cp.async.cg.shared.global [%0], [%1], 16;" :: "r"(s), "l"(g) : "memory");
}
#define CP_COMMIT() asm volatile("cp.async.commit_group;" ::: "memory")
#define CP_WAIT1()  asm volatile("cp.async.wait_group 1;" ::: "memory")

#define LDSM_X4(r, addr) \
    asm volatile("ldmatrix.sync.aligned.m8n8.x4.shared.b16 {%0,%1,%2,%3}, [%4];" \
        : "=r"((r)[0]), "=r"((r)[1]), "=r"((r)[2]), "=r"((r)[3]) : "r"(addr))

#define MMA_F16(d, a, bq) \
    asm volatile("mma.sync.aligned.m16n8k16.row.col.f32.f16.f16.f32 " \
        "{%0,%1,%2,%3}, {%4,%5,%6,%7}, {%8,%9}, {%0,%1,%2,%3};" \
        : "+f"((d)[0]), "+f"((d)[1]), "+f"((d)[2]), "+f"((d)[3]) \
        : "r"((a)[0]), "r"((a)[1]), "r"((a)[2]), "r"((a)[3]), \
          "r"((bq)[0]), "r"((bq)[1]))

// ---------------------------------------------------------------------------
// Prep: w [cout][cin][3][3] fp32 -> g_wT[which][tap][cout][cin] fp16
// ---------------------------------------------------------------------------
__global__ void prep_w_kernel(const float* __restrict__ w1, const float* __restrict__ w2)
{
    int t = blockIdx.x * 256 + threadIdx.x;
    int ci   = t & 255;
    int co   = (t >> 8) & 255;
    int rest = t >> 16;                  // 0..17
    int tap  = rest % 9;
    int which = rest / 9;
    const float* w = which ? w2 : w1;
    g_wT[t] = __float2half_rn(w[(size_t)(co * 256 + ci) * 9 + tap]);
}

// ---------------------------------------------------------------------------
// Transpose: kin NCHW fp32 -> g_xT NHWC fp16 (padded frame rows zeroed)
// grid (67, 4, 16), 256 threads. Tile: 64 ch x 64 pixels.
// ---------------------------------------------------------------------------
__global__ void transpose_x_kernel(const float* __restrict__ kin)
{
    __shared__ float s[64][65];
    const int b = blockIdx.z, c0 = blockIdx.y * 64, n0 = blockIdx.x * 64;
    const int tid = threadIdx.x;

    if (n0 < 4096) {
#pragma unroll
        for (int i = 0; i < 16; ++i) {
            int idx = tid + i * 256, c = idx >> 6, p = idx & 63;
            s[c][p] = kin[((size_t)(b * C_ + c0 + c) << 12) + n0 + p];
        }
        __syncthreads();
#pragma unroll
        for (int i = 0; i < 8; ++i) {
            int idx = tid + i * 256, n = idx >> 5, cp = (idx & 31) * 2;
            __half2 v = __floats2half2_rn(s[cp][n], s[cp + 1][n]);
            *(__half2*)&g_xT[((size_t)b * FR_ + n0 + n) * C_ + c0 + cp] = v;
        }
    } else {
#pragma unroll
        for (int i = 0; i < 8; ++i) {
            int idx = tid + i * 256, n = idx >> 5, cp = (idx & 31) * 2;
            *(__half2*)&g_xT[((size_t)b * FR_ + n0 + n) * C_ + c0 + cp] =
                __floats2half2_rn(0.f, 0.f);
        }
    }
}

// ---------------------------------------------------------------------------
// Implicit-GEMM conv via mma.sync fp16 (m16n8k16) + 3-stage cp.async + ldmatrix.
// Block: 256 threads (8 warps, 2 M-warps x 4 N-warps).
// CTA tile: M=128 pixels, N=128 couts. K-loop: 9 taps x 4 chunks of 64 cin.
// Warp tile: m64 x n32 = 4x4 mma x 4 k16-steps per chunk.
// Dynamic smem: 3 buffers of (A tile | B tile), 128 rows x 144B each.
// Mainloop (one barrier/iter): wait(1) -> sync -> stage(it+2) -> compute(it).
// FIRST: epilogue lrelu+bias -> g_h1T.  !FIRST: lrelu+bias + masked pool sum.
// ---------------------------------------------------------------------------
template <bool FIRST>
__global__ __launch_bounds__(256)
void conv_mma_kernel(const float* __restrict__ cbias)
{
    extern __shared__ __align__(16) char dsm[];
    __shared__ float sRed[2][128];

    const uint32_t sb = smem_u32(dsm);
    const int tid  = threadIdx.x;
    const int lane = tid & 31;
    const int wid  = tid >> 5;
    const int mwarp = wid >> 2;          // 0..1  (pixel 64-row half)
    const int nwarp = wid & 3;           // 0..3  (cout 32-col quarter)
    const int gid   = lane >> 2;         // 0..7
    const int tig   = lane & 3;          // 0..3

    const int ntile = blockIdx.x;
    const int b     = blockIdx.y;
    const int co0   = blockIdx.z * 128;
    const int n0    = ntile * 128;

    const __half* __restrict__ src  = FIRST ? g_xT : g_h1T;
    const __half* __restrict__ wsrc = g_wT + (FIRST ? 0 : (size_t)9 * 256 * 256);

    // staging: thread -> row rowS (0..127), 64B half (32 halves)
    const int rowS  = tid >> 1;
    const int halfS = (tid & 1) * 32;    // element offset within 64-half row
    const uint32_t stA = sb + (uint32_t)rowS * ROWB_ + (uint32_t)(tid & 1) * 64;
    const uint32_t stB = stA + TILEB_;

    // ldmatrix lane addresses (within tile) — validated b16 fragment layout
    const uint32_t aAddr = sb + (uint32_t)(mwarp * 64 + (lane & 15)) * ROWB_
                              + (uint32_t)(lane >> 4) * 16;
    const uint32_t bAddr = sb + TILEB_
                              + (uint32_t)(nwarp * 32 + ((lane >> 4) << 3) + (lane & 7)) * ROWB_
                              + (uint32_t)((lane >> 3) & 1) * 16;

    float acc[4][4][4];
#pragma unroll
    for (int mi = 0; mi < 4; ++mi)
#pragma unroll
        for (int ni = 0; ni < 4; ++ni)
#pragma unroll
            for (int j = 0; j < 4; ++j) acc[mi][ni][j] = 0.f;

    auto stage = [&](int it, int buf) {
        const int tap = it >> 2, ck = it & 3, cb = ck * 64;
        const int shift = (tap / 3) * 64 + (tap % 3);
        const uint32_t o = (uint32_t)buf * BUFB_;
        const __half* gA = src + ((size_t)(b * FR_ + n0 + shift + rowS)) * C_ + cb + halfS;
        const __half* gB = wsrc + ((size_t)(tap * 256 + co0 + rowS)) * C_ + cb + halfS;
#pragma unroll
        for (int j = 0; j < 4; ++j) cp16(stA + o + j * 16, gA + j * 8);
#pragma unroll
        for (int j = 0; j < 4; ++j) cp16(stB + o + j * 16, gB + j * 8);
    };

    // prologue: fill stages 0 and 1
    stage(0, 0); CP_COMMIT();
    stage(1, 1); CP_COMMIT();

    int buf = 0;
#pragma unroll 1
    for (int it = 0; it < 36; ++it) {
        CP_WAIT1();            // group for buf 'it' complete
        __syncthreads();       // visibility + all warps done reading buf (it-1)%3

        if (it < 34) {
            int nb = buf + 2; if (nb >= NSTAGE_) nb -= NSTAGE_;
            stage(it + 2, nb);
        }
        CP_COMMIT();

        const uint32_t Ab = aAddr + (uint32_t)buf * BUFB_;
        const uint32_t Bb = bAddr + (uint32_t)buf * BUFB_;

#pragma unroll
        for (int ks = 0; ks < 4; ++ks) {          // k16 steps: 4 x 32B columns
            uint32_t af[4][4];
#pragma unroll
            for (int mi = 0; mi < 4; ++mi)
                LDSM_X4(af[mi], Ab + (uint32_t)mi * (16 * ROWB_) + (uint32_t)ks * 32);
            uint32_t bf[4][2];
#pragma unroll
            for (int np = 0; np < 2; ++np) {
                uint32_t t4[4];
                LDSM_X4(t4, Bb + (uint32_t)np * (16 * ROWB_) + (uint32_t)ks * 32);
                bf[np * 2][0]     = t4[0]; bf[np * 2][1]     = t4[1];
                bf[np * 2 + 1][0] = t4[2]; bf[np * 2 + 1][1] = t4[3];
            }
#pragma unroll
            for (int mi = 0; mi < 4; ++mi)
#pragma unroll
                for (int ni = 0; ni < 4; ++ni)
                    MMA_F16(acc[mi][ni], af[mi], bf[ni]);
        }

        if (++buf >= NSTAGE_) buf = 0;
    }

    // ---- epilogue ----
    const int prow = mwarp * 64 + gid;                 // pixel row within tile (+8 for c2/c3)
    const int ccol = co0 + nwarp * 32 + tig * 2;       // cout (pair)

    float bv0[4], bv1[4];
#pragma unroll
    for (int ni = 0; ni < 4; ++ni) { bv0[ni] = cbias[ccol + ni * 8]; bv1[ni] = cbias[ccol + ni * 8 + 1]; }

    if (FIRST) {
#pragma unroll
        for (int mi = 0; mi < 4; ++mi) {
            int na = n0 + prow + mi * 16;
            int nb = na + 8;
#pragma unroll
            for (int ni = 0; ni < 4; ++ni) {
                int cc = ccol + ni * 8;
                __half2 va = __floats2half2_rn(lrelu(acc[mi][ni][0] + bv0[ni]),
                                               lrelu(acc[mi][ni][1] + bv1[ni]));
                __half2 vb = __floats2half2_rn(lrelu(acc[mi][ni][2] + bv0[ni]),
                                               lrelu(acc[mi][ni][3] + bv1[ni]));
                *(__half2*)&g_h1T[((size_t)(b * FR_ + na)) * C_ + cc] = va;
                *(__half2*)&g_h1T[((size_t)(b * FR_ + nb)) * C_ + cc] = vb;
            }
        }
    } else {
        float s0[4], s1[4];
#pragma unroll
        for (int ni = 0; ni < 4; ++ni) { s0[ni] = 0.f; s1[ni] = 0.f; }
#pragma unroll
        for (int mi = 0; mi < 4; ++mi) {
            int na = n0 + prow + mi * 16;
            int nb = na + 8;
            bool va = (na & 63) < 60;
            bool vb = (nb & 63) < 60;
#pragma unroll
            for (int ni = 0; ni < 4; ++ni) {
                if (va) { s0[ni] += lrelu(acc[mi][ni][0] + bv0[ni]);
                          s1[ni] += lrelu(acc[mi][ni][1] + bv1[ni]); }
                if (vb) { s0[ni] += lrelu(acc[mi][ni][2] + bv0[ni]);
                          s1[ni] += lrelu(acc[mi][ni][3] + bv1[ni]); }
            }
        }
#pragma unroll
        for (int off = 4; off <= 16; off <<= 1)
#pragma unroll
            for (int ni = 0; ni < 4; ++ni) {
                s0[ni] += __shfl_xor_sync(0xFFFFFFFFu, s0[ni], off);
                s1[ni] += __shfl_xor_sync(0xFFFFFFFFu, s1[ni], off);
            }
        if (lane < 4) {
#pragma unroll
            for (int ni = 0; ni < 4; ++ni) {
                sRed[mwarp][nwarp * 32 + ni * 8 + lane * 2]     = s0[ni];
                sRed[mwarp][nwarp * 32 + ni * 8 + lane * 2 + 1] = s1[ni];
            }
        }
        __syncthreads();
        if (tid < 128)
            g_ppart[((size_t)ntile * B_ + b) * C_ + co0 + tid] = sRed[0][tid] + sRed[1][tid];
    }
}

// ---------------------------------------------------------------------------
// reduce 30 tile partials -> pooled p[b][c] (divide by 60*60)
// ---------------------------------------------------------------------------
__global__ void reduce_p_kernel()
{
    int i = blockIdx.x * 256 + threadIdx.x;
    float s = 0.f;
#pragma unroll
    for (int t = 0; t < NT2_; ++t) s += g_ppart[(size_t)t * (B_ * C_) + i];
    g_p[i] = s * (1.0f / 3600.0f);
}

// ---------------------------------------------------------------------------
// kern[b][o] = sum_c p[b][c] * w3[o][c] + b3[o]
// ---------------------------------------------------------------------------
__global__ void kern_gemm_kernel(const float* __restrict__ w3, const float* __restrict__ b3)
{
    __shared__ float sp[B_ * C_];
    const int tid = threadIdx.x, warp = tid >> 5, lane = tid & 31;
    for (int i = tid; i < B_ * C_; i += 256) sp[i] = g_p[i];
    __syncthreads();

    int o = blockIdx.x * 8 + warp;
    float wreg[8];
#pragma unroll
    for (int i = 0; i < 8; ++i) wreg[i] = w3[(size_t)o * C_ + lane + i * 32];
    float acc[B_];
#pragma unroll
    for (int b = 0; b < B_; ++b) acc[b] = 0.f;
#pragma unroll
    for (int i = 0; i < 8; ++i) {
        int c = lane + i * 32;
        float wv = wreg[i];
#pragma unroll
        for (int b = 0; b < B_; ++b) acc[b] = fmaf(wv, sp[b * C_ + c], acc[b]);
    }
#pragma unroll
    for (int off = 16; off > 0; off >>= 1)
#pragma unroll
        for (int b = 0; b < B_; ++b) acc[b] += __shfl_xor_sync(0xFFFFFFFFu, acc[b], off);
    if (lane == 0) {
        float bb = b3[o];
#pragma unroll
        for (int b = 0; b < B_; ++b) g_kern[b * (9 * C_) + o] = acc[b] + bb;
    }
}

// ---------------------------------------------------------------------------
// Depthwise 3x3 SAME conv, per-(b,c) kernel + bias. One block per (b,c).
// ---------------------------------------------------------------------------
__global__ __launch_bounds__(256)
void dwconv_kernel(const float* __restrict__ x, const float* __restrict__ bias,
                   float* __restrict__ out)
{
    __shared__ float sx[H_ * W_];
    __shared__ float sk[9];
    const int tid = threadIdx.x;
    const int bc = blockIdx.x, b = bc >> 8, c = bc & 255;

    const float* xin = x + (size_t)bc * (H_ * W_);
    for (int i = tid; i < (H_ * W_) / 4; i += 256)
        reinterpret_cast<float4*>(sx)[i] = reinterpret_cast<const float4*>(xin)[i];
    if (tid < 9) sk[tid] = g_kern[b * (9 * C_) + c * 9 + tid];
    __syncthreads();

    const float bv = bias[c];
    float k[9];
#pragma unroll
    for (int i = 0; i < 9; ++i) k[i] = sk[i];

    for (int p = tid; p < H_ * W_; p += 256) {
        int y = p >> 6, xx = p & 63;
        float s = bv;
#pragma unroll
        for (int ky = 0; ky < 3; ++ky) {
            int yy = y + ky - 1;
            if (yy < 0 || yy >= H_) continue;
#pragma unroll
            for (int kx = 0; kx < 3; ++kx) {
                int xc = xx + kx - 1;
                if (xc < 0 || xc >= W_) continue;
                s = fmaf(k[ky * 3 + kx], sx[yy * W_ + xc], s);
            }
        }
        out[(size_t)bc * (H_ * W_) + p] = s;
    }
}

// ---------------------------------------------------------------------------
// Launch. Inputs: x, kin, w1, b1, w2, b2, w3, b3, bias
// ---------------------------------------------------------------------------
extern "C" void kernel_launch(void* const* d_in, const int* in_sizes, int n_in,
                              void* d_out, int out_size)
{
    const float* x    = (const float*)d_in[0];
    const float* kin  = (const float*)d_in[1];
    const float* w1   = (const float*)d_in[2];
    const float* b1   = (const float*)d_in[3];
    const float* w2   = (const float*)d_in[4];
    const float* b2   = (const float*)d_in[5];
    const float* w3   = (const float*)d_in[6];
    const float* b3   = (const float*)d_in[7];
    const float* bias = (const float*)d_in[8];
    float* out = (float*)d_out;

    const int SMEM_CONV = NSTAGE_ * BUFB_;    // 110592 B dynamic
    cudaFuncSetAttribute(conv_mma_kernel<true>,  cudaFuncAttributeMaxDynamicSharedMemorySize, SMEM_CONV);
    cudaFuncSetAttribute(conv_mma_kernel<false>, cudaFuncAttributeMaxDynamicSharedMemorySize, SMEM_CONV);

    prep_w_kernel<<<2 * 9 * 256, 256>>>(w1, w2);
    transpose_x_kernel<<<dim3(67, 4, 16), 256>>>(kin);
    conv_mma_kernel<true ><<<dim3(NT1_, B_, 2), 256, SMEM_CONV>>>(b1);
    conv_mma_kernel<false><<<dim3(NT2_, B_, 2), 256, SMEM_CONV>>>(b2);
    reduce_p_kernel<<<B_ * C_ / 256, 256>>>();
    kern_gemm_kernel<<<(9 * C_) / 8, 256>>>(w3, b3);
    dwconv_kernel<<<B_ * C_, 256>>>(x, bias, out);
}